// round 4
// baseline (speedup 1.0000x reference)
#include <cuda_runtime.h>

// LSTMModel: 2-layer LSTM (B=4096, T=512, D=8, H=64) + FC(H->1).
// One persistent CTA per 32 batch rows; both layers fused per timestep.
// Weights live in SMEM (permuted/transposed); h-state transposed in SMEM;
// c-state in registers; inner GEMMs use packed fma.rn.f32x2 (2x FFMA rate).

#define Bv 4096
#define Tv 512
#define Dv 8
#define Hv 64
#define TILE_B 32
#define NTH 256
#define HS 36            // padded row stride (floats) for h state: 144B, 16B aligned

typedef unsigned long long ull;

// ---- packed f32x2 helpers (ptxas never auto-fuses these) ----
__device__ __forceinline__ void fma2(ull &d, ull a, ull b) {
    asm("fma.rn.f32x2 %0, %1, %2, %0;" : "+l"(d) : "l"(a), "l"(b));
}
__device__ __forceinline__ ull dup2(float x) {
    ull r; asm("mov.b64 %0, {%1, %1};" : "=l"(r) : "f"(x)); return r;
}
__device__ __forceinline__ void unpack2(ull v, float &lo, float &hi) {
    asm("mov.b64 {%0, %1}, %2;" : "=f"(lo), "=f"(hi) : "l"(v));
}

// ---- fast activations (MUFU EX2 + RCP; rel err ~1e-6, far under 1e-3) ----
__device__ __forceinline__ float sig_(float x) {
    return __fdividef(1.0f, 1.0f + __expf(-x));
}
__device__ __forceinline__ float tanh_(float x) {
    return __fdividef(2.0f, 1.0f + __expf(-2.0f * x)) - 1.0f;
}

// ---- SMEM layout (float offsets) ----
#define OFF_WT0 0                    // Whh0^T permuted: [64][256]
#define OFF_WI1 16384                // Wih1^T permuted: [64][256]
#define OFF_WT1 32768                // Whh1^T permuted: [64][256]
#define OFF_WX0 49152                // Wih0^T permuted: [8][256]
#define OFF_B0  51200                // bih0+bhh0 permuted: [256]
#define OFF_B1  51456                // bih1+bhh1 permuted: [256]
#define OFF_HT0 51712                // h state layer0: [64][HS]
#define OFF_HT1 54016                // h state layer1: [64][HS]
#define OFF_XS  56320                // x staging double buffer: [2][8][32]
#define SMEM_FLOATS 56832            // 227328 bytes < 232448 opt-in limit

// Accumulate acc[16] (4 row-pairs x 4 gates) += h[K x rows] * W[K x 256]
// hsm rows stride HSTR; wsm rows stride 256 (permuted gate layout).
template<int K, int HSTR>
__device__ __forceinline__ void gemm_acc(ull* acc, const float* hsm, const float* wsm,
                                         int hoff, int tg)
{
    const float* hp = hsm + hoff;
    const float* wp = wsm + tg * 4;
    #pragma unroll 8
    for (int k = 0; k < K; k++) {
        ulonglong2 hA = *reinterpret_cast<const ulonglong2*>(hp + k * HSTR);     // rows 0-3
        ulonglong2 hB = *reinterpret_cast<const ulonglong2*>(hp + k * HSTR + 4); // rows 4-7
        float4 wv = *reinterpret_cast<const float4*>(wp + k * 256);
        ull w0 = dup2(wv.x), w1 = dup2(wv.y), w2 = dup2(wv.z), w3 = dup2(wv.w);
        fma2(acc[0],  hA.x, w0); fma2(acc[1],  hA.x, w1); fma2(acc[2],  hA.x, w2); fma2(acc[3],  hA.x, w3);
        fma2(acc[4],  hA.y, w0); fma2(acc[5],  hA.y, w1); fma2(acc[6],  hA.y, w2); fma2(acc[7],  hA.y, w3);
        fma2(acc[8],  hB.x, w0); fma2(acc[9],  hB.x, w1); fma2(acc[10], hB.x, w2); fma2(acc[11], hB.x, w3);
        fma2(acc[12], hB.y, w0); fma2(acc[13], hB.y, w1); fma2(acc[14], hB.y, w2); fma2(acc[15], hB.y, w3);
    }
}

__device__ __forceinline__ void init_acc(ull* acc, const float* bs, int tg)
{
    const float4 bv = *reinterpret_cast<const float4*>(bs + tg * 4);
    ull b0 = dup2(bv.x), b1 = dup2(bv.y), b2 = dup2(bv.z), b3 = dup2(bv.w);
    #pragma unroll
    for (int p = 0; p < 4; p++) {
        acc[p*4+0] = b0; acc[p*4+1] = b1; acc[p*4+2] = b2; acc[p*4+3] = b3;
    }
}

// LSTM cell elementwise update: gates -> c (regs), h -> SMEM (transposed).
__device__ __forceinline__ void cell_update(const ull* acc, float* c, float* hdst)
{
    #pragma unroll
    for (int p = 0; p < 4; p++) {
        float zi0, zi1, zf0, zf1, zg0, zg1, zo0, zo1;
        unpack2(acc[p*4+0], zi0, zi1);
        unpack2(acc[p*4+1], zf0, zf1);
        unpack2(acc[p*4+2], zg0, zg1);
        unpack2(acc[p*4+3], zo0, zo1);
        float cA = sig_(zf0) * c[2*p]     + sig_(zi0) * tanh_(zg0);
        float cB = sig_(zf1) * c[2*p + 1] + sig_(zi1) * tanh_(zg1);
        c[2*p]     = cA;
        c[2*p + 1] = cB;
        hdst[2*p]     = sig_(zo0) * tanh_(cA);
        hdst[2*p + 1] = sig_(zo1) * tanh_(cB);
    }
}

__global__ void __launch_bounds__(NTH, 1)
lstm_kernel(const float* __restrict__ x,
            const float* __restrict__ Wih0, const float* __restrict__ Whh0,
            const float* __restrict__ bih0, const float* __restrict__ bhh0,
            const float* __restrict__ Wih1, const float* __restrict__ Whh1,
            const float* __restrict__ bih1, const float* __restrict__ bhh1,
            const float* __restrict__ Wfc,  const float* __restrict__ bfc,
            float* __restrict__ out)
{
    extern __shared__ float sm[];
    float* Wt0 = sm + OFF_WT0;
    float* Wi1 = sm + OFF_WI1;
    float* Wt1 = sm + OFF_WT1;
    float* Wx0 = sm + OFF_WX0;
    float* b0s = sm + OFF_B0;
    float* b1s = sm + OFF_B1;
    float* ht0 = sm + OFF_HT0;
    float* ht1 = sm + OFF_HT1;
    float* xs  = sm + OFF_XS;

    const int tid   = threadIdx.x;
    const int tg    = tid & 63;          // j column (0..63)
    const int tb    = tid >> 6;          // row-group (0..3), 8 rows each
    const int hoff  = tb * 8;
    const int bbase = blockIdx.x * TILE_B;

    // ---- load + permute weights into SMEM ----
    // permuted col pg for original gate-row g = q*64+j  ->  pg = j*4+q
    for (int idx = tid; idx < 16384; idx += NTH) {
        int g = idx >> 6, k = idx & 63;
        int pg = ((g & 63) << 2) | (g >> 6);
        Wt0[k * 256 + pg] = Whh0[idx];
        Wi1[k * 256 + pg] = Wih1[idx];
        Wt1[k * 256 + pg] = Whh1[idx];
    }
    for (int idx = tid; idx < 2048; idx += NTH) {
        int g = idx >> 3, d = idx & 7;
        int pg = ((g & 63) << 2) | (g >> 6);
        Wx0[d * 256 + pg] = Wih0[idx];
    }
    {
        int g = tid;                     // NTH == 256 == 4H
        int pg = ((g & 63) << 2) | (g >> 6);
        b0s[pg] = bih0[g] + bhh0[g];
        b1s[pg] = bih1[g] + bhh1[g];
    }
    for (int idx = tid; idx < 64 * HS; idx += NTH) { ht0[idx] = 0.0f; ht1[idx] = 0.0f; }

    // stage x for t=0 into buffer 0, transposed [d][row]
    const int xr = tid >> 3, xd = tid & 7;
    const float* xptr = x + (size_t)(bbase + xr) * (Tv * Dv) + xd;
    xs[xd * 32 + xr] = xptr[0];
    __syncthreads();

    float c0[8], c1[8];
    #pragma unroll
    for (int i = 0; i < 8; i++) { c0[i] = 0.0f; c1[i] = 0.0f; }

    ull acc[16];

    for (int t = 0; t < Tv; t++) {
        const int cur = t & 1;
        const float* xcur = xs + cur * 256;
        float*       xnxt = xs + (cur ^ 1) * 256;

        // ---- layer 0: z0 = b0 + x_t@Wih0^T + h0@Whh0^T ----
        init_acc(acc, b0s, tg);
        gemm_acc<Dv, 32>(acc, xcur, Wx0, hoff, tg);
        float xreg = 0.0f;
        if (t + 1 < Tv) xreg = __ldg(xptr + (size_t)(t + 1) * Dv);  // prefetch under GEMM
        gemm_acc<Hv, HS>(acc, ht0, Wt0, hoff, tg);
        __syncthreads();                                  // (1) reads of ht0/xcur done

        cell_update(acc, c0, ht0 + tg * HS + hoff);       // write new h0 (transposed)
        xnxt[xd * 32 + xr] = xreg;                        // stage x for t+1
        __syncthreads();                                  // (2) new h0 (+ xnxt) visible

        // ---- layer 1: z1 = b1 + h0_new@Wih1^T + h1@Whh1^T ----
        init_acc(acc, b1s, tg);
        gemm_acc<Hv, HS>(acc, ht0, Wi1, hoff, tg);
        gemm_acc<Hv, HS>(acc, ht1, Wt1, hoff, tg);
        __syncthreads();                                  // (3) reads of ht1 done

        cell_update(acc, c1, ht1 + tg * HS + hoff);       // write new h1
        // NOTE: no 4th sync — next-step reads of ht1 are ordered by syncs (1)+(2)
        // of step t+1; WAR on ht1 is covered by sync (3). 
    }
    __syncthreads();                                      // h1 final visible for FC

    // ---- FC: out[b] = h1_final[b,:] . Wfc + bfc ----
    if (tid < TILE_B) {
        float s = 0.0f;
        #pragma unroll
        for (int j = 0; j < Hv; j++) s += ht1[j * HS + tid] * __ldg(Wfc + j);
        out[bbase + tid] = s + __ldg(bfc);
    }
}

extern "C" void kernel_launch(void* const* d_in, const int* in_sizes, int n_in,
                              void* d_out, int out_size)
{
    const float* x    = (const float*)d_in[0];
    const float* Wih0 = (const float*)d_in[1];
    const float* Whh0 = (const float*)d_in[2];
    const float* bih0 = (const float*)d_in[3];
    const float* bhh0 = (const float*)d_in[4];
    const float* Wih1 = (const float*)d_in[5];
    const float* Whh1 = (const float*)d_in[6];
    const float* bih1 = (const float*)d_in[7];
    const float* bhh1 = (const float*)d_in[8];
    const float* Wfc  = (const float*)d_in[9];
    const float* bfc  = (const float*)d_in[10];
    float* out = (float*)d_out;

    size_t shm = (size_t)SMEM_FLOATS * sizeof(float);   // 227328 B
    cudaFuncSetAttribute(lstm_kernel, cudaFuncAttributeMaxDynamicSharedMemorySize, (int)shm);
    lstm_kernel<<<Bv / TILE_B, NTH, shm>>>(x, Wih0, Whh0, bih0, bhh0,
                                           Wih1, Whh1, bih1, bhh1, Wfc, bfc, out);
}

// round 5
// speedup vs baseline: 1.0726x; 1.0726x over previous
#include <cuda_runtime.h>

// LSTMModel: 2-layer LSTM (B=4096, T=512, D=8, H=64) + FC(H->1).
// One persistent CTA per 32 batch rows; both layers fused per timestep.
// R5: 2 barriers/step (was 3), layer-1 recurrent GEMM hoisted to hide
// cell_update latency; MUFU.TANH activations (tanh.approx.f32).

#define Bv 4096
#define Tv 512
#define Dv 8
#define Hv 64
#define TILE_B 32
#define NTH 256
#define HS 36            // padded row stride (floats) for h state: 144B, 16B aligned

typedef unsigned long long ull;

// ---- packed f32x2 helpers (ptxas never auto-fuses these) ----
__device__ __forceinline__ void fma2(ull &d, ull a, ull b) {
    asm("fma.rn.f32x2 %0, %1, %2, %0;" : "+l"(d) : "l"(a), "l"(b));
}
__device__ __forceinline__ ull dup2(float x) {
    ull r; asm("mov.b64 %0, {%1, %1};" : "=l"(r) : "f"(x)); return r;
}
__device__ __forceinline__ void unpack2(ull v, float &lo, float &hi) {
    asm("mov.b64 {%0, %1}, %2;" : "=f"(lo), "=f"(hi) : "l"(v));
}

// ---- activations via single-instruction MUFU.TANH ----
__device__ __forceinline__ float tanh_(float x) {
    float r; asm("tanh.approx.f32 %0, %1;" : "=f"(r) : "f"(x)); return r;
}
__device__ __forceinline__ float sig_(float x) {
    return fmaf(tanh_(0.5f * x), 0.5f, 0.5f);
}

// ---- SMEM layout (float offsets) ----
#define OFF_WT0 0                    // Whh0^T permuted: [64][256]
#define OFF_WI1 16384                // Wih1^T permuted: [64][256]
#define OFF_WT1 32768                // Whh1^T permuted: [64][256]
#define OFF_WX0 49152                // Wih0^T permuted: [8][256]
#define OFF_B0  51200                // bih0+bhh0 permuted: [256]
#define OFF_B1  51456                // bih1+bhh1 permuted: [256]
#define OFF_HT0 51712                // h state layer0: [64][HS]
#define OFF_HT1 54016                // h state layer1: [64][HS]
#define OFF_XS  56320                // x staging double buffer: [2][8][32]
#define SMEM_FLOATS 56832            // 227328 bytes < 232448 opt-in limit

// Accumulate acc[16] (4 row-pairs x 4 gates) += h[K x rows] * W[K x 256]
template<int K, int HSTR>
__device__ __forceinline__ void gemm_acc(ull* acc, const float* hsm, const float* wsm,
                                         int hoff, int tg)
{
    const float* hp = hsm + hoff;
    const float* wp = wsm + tg * 4;
    #pragma unroll 8
    for (int k = 0; k < K; k++) {
        ulonglong2 hA = *reinterpret_cast<const ulonglong2*>(hp + k * HSTR);     // rows 0-3
        ulonglong2 hB = *reinterpret_cast<const ulonglong2*>(hp + k * HSTR + 4); // rows 4-7
        float4 wv = *reinterpret_cast<const float4*>(wp + k * 256);
        ull w0 = dup2(wv.x), w1 = dup2(wv.y), w2 = dup2(wv.z), w3 = dup2(wv.w);
        fma2(acc[0],  hA.x, w0); fma2(acc[1],  hA.x, w1); fma2(acc[2],  hA.x, w2); fma2(acc[3],  hA.x, w3);
        fma2(acc[4],  hA.y, w0); fma2(acc[5],  hA.y, w1); fma2(acc[6],  hA.y, w2); fma2(acc[7],  hA.y, w3);
        fma2(acc[8],  hB.x, w0); fma2(acc[9],  hB.x, w1); fma2(acc[10], hB.x, w2); fma2(acc[11], hB.x, w3);
        fma2(acc[12], hB.y, w0); fma2(acc[13], hB.y, w1); fma2(acc[14], hB.y, w2); fma2(acc[15], hB.y, w3);
    }
}

__device__ __forceinline__ void init_acc(ull* acc, const float* bs, int tg)
{
    const float4 bv = *reinterpret_cast<const float4*>(bs + tg * 4);
    ull b0 = dup2(bv.x), b1 = dup2(bv.y), b2 = dup2(bv.z), b3 = dup2(bv.w);
    #pragma unroll
    for (int p = 0; p < 4; p++) {
        acc[p*4+0] = b0; acc[p*4+1] = b1; acc[p*4+2] = b2; acc[p*4+3] = b3;
    }
}

// LSTM cell elementwise update: gates -> c (regs), h -> SMEM (transposed).
__device__ __forceinline__ void cell_update(const ull* acc, float* c, float* hdst)
{
    #pragma unroll
    for (int p = 0; p < 4; p++) {
        float zi0, zi1, zf0, zf1, zg0, zg1, zo0, zo1;
        unpack2(acc[p*4+0], zi0, zi1);
        unpack2(acc[p*4+1], zf0, zf1);
        unpack2(acc[p*4+2], zg0, zg1);
        unpack2(acc[p*4+3], zo0, zo1);
        float cA = sig_(zf0) * c[2*p]     + sig_(zi0) * tanh_(zg0);
        float cB = sig_(zf1) * c[2*p + 1] + sig_(zi1) * tanh_(zg1);
        c[2*p]     = cA;
        c[2*p + 1] = cB;
        hdst[2*p]     = sig_(zo0) * tanh_(cA);
        hdst[2*p + 1] = sig_(zo1) * tanh_(cB);
    }
}

__global__ void __launch_bounds__(NTH, 1)
lstm_kernel(const float* __restrict__ x,
            const float* __restrict__ Wih0, const float* __restrict__ Whh0,
            const float* __restrict__ bih0, const float* __restrict__ bhh0,
            const float* __restrict__ Wih1, const float* __restrict__ Whh1,
            const float* __restrict__ bih1, const float* __restrict__ bhh1,
            const float* __restrict__ Wfc,  const float* __restrict__ bfc,
            float* __restrict__ out)
{
    extern __shared__ float sm[];
    float* Wt0 = sm + OFF_WT0;
    float* Wi1 = sm + OFF_WI1;
    float* Wt1 = sm + OFF_WT1;
    float* Wx0 = sm + OFF_WX0;
    float* b0s = sm + OFF_B0;
    float* b1s = sm + OFF_B1;
    float* ht0 = sm + OFF_HT0;
    float* ht1 = sm + OFF_HT1;
    float* xs  = sm + OFF_XS;

    const int tid   = threadIdx.x;
    const int tg    = tid & 63;          // j column (0..63)
    const int tb    = tid >> 6;          // row-group (0..3), 8 rows each
    const int hoff  = tb * 8;
    const int bbase = blockIdx.x * TILE_B;

    // ---- load + permute weights into SMEM ----
    // permuted col pg for original gate-row g = q*64+j  ->  pg = j*4+q
    for (int idx = tid; idx < 16384; idx += NTH) {
        int g = idx >> 6, k = idx & 63;
        int pg = ((g & 63) << 2) | (g >> 6);
        Wt0[k * 256 + pg] = Whh0[idx];
        Wi1[k * 256 + pg] = Wih1[idx];
        Wt1[k * 256 + pg] = Whh1[idx];
    }
    for (int idx = tid; idx < 2048; idx += NTH) {
        int g = idx >> 3, d = idx & 7;
        int pg = ((g & 63) << 2) | (g >> 6);
        Wx0[d * 256 + pg] = Wih0[idx];
    }
    {
        int g = tid;                     // NTH == 256 == 4H
        int pg = ((g & 63) << 2) | (g >> 6);
        b0s[pg] = bih0[g] + bhh0[g];
        b1s[pg] = bih1[g] + bhh1[g];
    }
    for (int idx = tid; idx < 64 * HS; idx += NTH) { ht0[idx] = 0.0f; ht1[idx] = 0.0f; }

    // stage x for t=0 into buffer 0, transposed [d][row]
    const int xr = tid >> 3, xd = tid & 7;
    const float* xptr = x + (size_t)(bbase + xr) * (Tv * Dv) + xd;
    xs[xd * 32 + xr] = xptr[0];
    __syncthreads();

    float c0[8], c1[8];
    #pragma unroll
    for (int i = 0; i < 8; i++) { c0[i] = 0.0f; c1[i] = 0.0f; }

    ull acc[16];

    for (int t = 0; t < Tv; t++) {
        const int cur = t & 1;
        const float* xcur = xs + cur * 256;
        float*       xnxt = xs + (cur ^ 1) * 256;

        // ---- (1) z0 = b0 + x_t@Wih0^T + h0@Whh0^T ----
        init_acc(acc, b0s, tg);
        gemm_acc<Dv, 32>(acc, xcur, Wx0, hoff, tg);
        float xreg = 0.0f;
        if (t + 1 < Tv) xreg = __ldg(xptr + (size_t)(t + 1) * Dv);  // prefetch under GEMM
        gemm_acc<Hv, HS>(acc, ht0, Wt0, hoff, tg);
        __syncthreads();                       // sync1: reads of ht0/xcur/ht1(prev step) done

        // ---- (2) layer-0 cell + stage x(t+1) ----
        cell_update(acc, c0, ht0 + tg * HS + hoff);   // write new h0 (in place)
        xnxt[xd * 32 + xr] = xreg;

        // ---- (3) layer-1 recurrent part: z1 = b1 + h1_prev@Whh1^T ----
        // Depends only on ht1 from last step (published by sync1); runs while
        // other warps finish cell_update0, absorbing its latency/skew.
        init_acc(acc, b1s, tg);
        gemm_acc<Hv, HS>(acc, ht1, Wt1, hoff, tg);
        __syncthreads();                       // sync2: h0' visible; ht1 reads done

        // ---- (4) z1 += h0_new@Wih1^T ; layer-1 cell ----
        gemm_acc<Hv, HS>(acc, ht0, Wi1, hoff, tg);
        cell_update(acc, c1, ht1 + tg * HS + hoff);   // write new h1 (in place)
        // No 3rd sync: next step's ht1 reads are ordered by next sync1;
        // WAR on ht1 covered by sync2; WAR on ht0 (reads in (4)) by next sync1.
    }
    __syncthreads();                           // final h1 visible for FC

    // ---- FC: out[b] = h1_final[b,:] . Wfc + bfc ----
    if (tid < TILE_B) {
        float s = 0.0f;
        #pragma unroll
        for (int j = 0; j < Hv; j++) s += ht1[j * HS + tid] * __ldg(Wfc + j);
        out[bbase + tid] = s + __ldg(bfc);
    }
}

extern "C" void kernel_launch(void* const* d_in, const int* in_sizes, int n_in,
                              void* d_out, int out_size)
{
    const float* x    = (const float*)d_in[0];
    const float* Wih0 = (const float*)d_in[1];
    const float* Whh0 = (const float*)d_in[2];
    const float* bih0 = (const float*)d_in[3];
    const float* bhh0 = (const float*)d_in[4];
    const float* Wih1 = (const float*)d_in[5];
    const float* Whh1 = (const float*)d_in[6];
    const float* bih1 = (const float*)d_in[7];
    const float* bhh1 = (const float*)d_in[8];
    const float* Wfc  = (const float*)d_in[9];
    const float* bfc  = (const float*)d_in[10];
    float* out = (float*)d_out;

    size_t shm = (size_t)SMEM_FLOATS * sizeof(float);   // 227328 B
    cudaFuncSetAttribute(lstm_kernel, cudaFuncAttributeMaxDynamicSharedMemorySize, (int)shm);
    lstm_kernel<<<Bv / TILE_B, NTH, shm>>>(x, Wih0, Whh0, bih0, bhh0,
                                           Wih1, Whh1, bih1, bhh1, Wfc, bfc, out);
}

// round 6
// speedup vs baseline: 1.1352x; 1.0584x over previous
#include <cuda_runtime.h>

// LSTMModel: 2-layer LSTM (B=4096, T=512, D=8, H=64) + FC(H->1).
// One persistent CTA per 32 batch rows; both layers fused per timestep.
// R6: per-step syncs are 2-warp NAMED barriers (all per-step dataflow is
// group-local); dual acc register sets + rotated loop so both cell_updates
// (MUFU-heavy) overlap a full 64-k GEMM of independent FMA work.

#define Bv 4096
#define Tv 512
#define Dv 8
#define Hv 64
#define TILE_B 32
#define NTH 256
#define HS 36            // padded row stride (floats) for h state: 144B, 16B aligned

typedef unsigned long long ull;

// ---- packed f32x2 helpers ----
__device__ __forceinline__ void fma2(ull &d, ull a, ull b) {
    asm("fma.rn.f32x2 %0, %1, %2, %0;" : "+l"(d) : "l"(a), "l"(b));
}
__device__ __forceinline__ ull dup2(float x) {
    ull r; asm("mov.b64 %0, {%1, %1};" : "=l"(r) : "f"(x)); return r;
}
__device__ __forceinline__ void unpack2(ull v, float &lo, float &hi) {
    asm("mov.b64 {%0, %1}, %2;" : "=f"(lo), "=f"(hi) : "l"(v));
}

// ---- activations via single-instruction MUFU.TANH ----
__device__ __forceinline__ float tanh_(float x) {
    float r; asm("tanh.approx.f32 %0, %1;" : "=f"(r) : "f"(x)); return r;
}
__device__ __forceinline__ float sig_(float x) {
    return fmaf(tanh_(0.5f * x), 0.5f, 0.5f);
}

// 2-warp group barrier (ids 1..4). All per-step producer/consumer pairs are
// within one 64-thread row-group, so no CTA-wide sync is needed in the loop.
#define GBAR(id) asm volatile("bar.sync %0, 64;" :: "r"(id) : "memory")

// ---- SMEM layout (float offsets) ----
#define OFF_WT0 0                    // Whh0^T permuted: [64][256]
#define OFF_WI1 16384                // Wih1^T permuted: [64][256]
#define OFF_WT1 32768                // Whh1^T permuted: [64][256]
#define OFF_WX0 49152                // Wih0^T permuted: [8][256]
#define OFF_B0  51200                // bih0+bhh0 permuted: [256]
#define OFF_B1  51456                // bih1+bhh1 permuted: [256]
#define OFF_HT0 51712                // h state layer0: [64][HS]
#define OFF_HT1 54016                // h state layer1: [64][HS]
#define OFF_XS  56320                // x staging double buffer: [2][8][32]
#define SMEM_FLOATS 56832            // 227328 bytes < 232448 opt-in limit

// Accumulate acc[16] (4 row-pairs x 4 gates) += h[K x rows] * W[K x 256]
template<int K, int HSTR>
__device__ __forceinline__ void gemm_acc(ull* acc, const float* hsm, const float* wsm,
                                         int hoff, int tg)
{
    const float* hp = hsm + hoff;
    const float* wp = wsm + tg * 4;
    #pragma unroll 8
    for (int k = 0; k < K; k++) {
        ulonglong2 hA = *reinterpret_cast<const ulonglong2*>(hp + k * HSTR);     // rows 0-3
        ulonglong2 hB = *reinterpret_cast<const ulonglong2*>(hp + k * HSTR + 4); // rows 4-7
        float4 wv = *reinterpret_cast<const float4*>(wp + k * 256);
        ull w0 = dup2(wv.x), w1 = dup2(wv.y), w2 = dup2(wv.z), w3 = dup2(wv.w);
        fma2(acc[0],  hA.x, w0); fma2(acc[1],  hA.x, w1); fma2(acc[2],  hA.x, w2); fma2(acc[3],  hA.x, w3);
        fma2(acc[4],  hA.y, w0); fma2(acc[5],  hA.y, w1); fma2(acc[6],  hA.y, w2); fma2(acc[7],  hA.y, w3);
        fma2(acc[8],  hB.x, w0); fma2(acc[9],  hB.x, w1); fma2(acc[10], hB.x, w2); fma2(acc[11], hB.x, w3);
        fma2(acc[12], hB.y, w0); fma2(acc[13], hB.y, w1); fma2(acc[14], hB.y, w2); fma2(acc[15], hB.y, w3);
    }
}

__device__ __forceinline__ void init_acc(ull* acc, const float* bs, int tg)
{
    const float4 bv = *reinterpret_cast<const float4*>(bs + tg * 4);
    ull b0 = dup2(bv.x), b1 = dup2(bv.y), b2 = dup2(bv.z), b3 = dup2(bv.w);
    #pragma unroll
    for (int p = 0; p < 4; p++) {
        acc[p*4+0] = b0; acc[p*4+1] = b1; acc[p*4+2] = b2; acc[p*4+3] = b3;
    }
}

// LSTM cell elementwise update: gates -> c (regs), h -> SMEM (transposed).
__device__ __forceinline__ void cell_update(const ull* acc, float* c, float* hdst)
{
    #pragma unroll
    for (int p = 0; p < 4; p++) {
        float zi0, zi1, zf0, zf1, zg0, zg1, zo0, zo1;
        unpack2(acc[p*4+0], zi0, zi1);
        unpack2(acc[p*4+1], zf0, zf1);
        unpack2(acc[p*4+2], zg0, zg1);
        unpack2(acc[p*4+3], zo0, zo1);
        float cA = sig_(zf0) * c[2*p]     + sig_(zi0) * tanh_(zg0);
        float cB = sig_(zf1) * c[2*p + 1] + sig_(zi1) * tanh_(zg1);
        c[2*p]     = cA;
        c[2*p + 1] = cB;
        hdst[2*p]     = sig_(zo0) * tanh_(cA);
        hdst[2*p + 1] = sig_(zo1) * tanh_(cB);
    }
}

__global__ void __launch_bounds__(NTH, 1)
lstm_kernel(const float* __restrict__ x,
            const float* __restrict__ Wih0, const float* __restrict__ Whh0,
            const float* __restrict__ bih0, const float* __restrict__ bhh0,
            const float* __restrict__ Wih1, const float* __restrict__ Whh1,
            const float* __restrict__ bih1, const float* __restrict__ bhh1,
            const float* __restrict__ Wfc,  const float* __restrict__ bfc,
            float* __restrict__ out)
{
    extern __shared__ float sm[];
    float* Wt0 = sm + OFF_WT0;
    float* Wi1 = sm + OFF_WI1;
    float* Wt1 = sm + OFF_WT1;
    float* Wx0 = sm + OFF_WX0;
    float* b0s = sm + OFF_B0;
    float* b1s = sm + OFF_B1;
    float* ht0 = sm + OFF_HT0;
    float* ht1 = sm + OFF_HT1;
    float* xs  = sm + OFF_XS;

    const int tid   = threadIdx.x;
    const int tg    = tid & 63;          // j column (0..63)
    const int tb    = tid >> 6;          // row-group (0..3), 8 rows each
    const int hoff  = tb * 8;
    const int gbar  = tb + 1;            // named barrier id for this group
    const int bbase = blockIdx.x * TILE_B;

    // ---- load + permute weights into SMEM ----
    // permuted col pg for original gate-row g = q*64+j  ->  pg = j*4+q
    for (int idx = tid; idx < 16384; idx += NTH) {
        int g = idx >> 6, k = idx & 63;
        int pg = ((g & 63) << 2) | (g >> 6);
        Wt0[k * 256 + pg] = Whh0[idx];
        Wi1[k * 256 + pg] = Wih1[idx];
        Wt1[k * 256 + pg] = Whh1[idx];
    }
    for (int idx = tid; idx < 2048; idx += NTH) {
        int g = idx >> 3, d = idx & 7;
        int pg = ((g & 63) << 2) | (g >> 6);
        Wx0[d * 256 + pg] = Wih0[idx];
    }
    {
        int g = tid;                     // NTH == 256 == 4H
        int pg = ((g & 63) << 2) | (g >> 6);
        b0s[pg] = bih0[g] + bhh0[g];
        b1s[pg] = bih1[g] + bhh1[g];
    }
    for (int idx = tid; idx < 64 * HS; idx += NTH) { ht0[idx] = 0.0f; ht1[idx] = 0.0f; }

    // stage x for t=0 into buffer 0, transposed [d][row]
    const int xr = tid >> 3, xd = tid & 7;
    const float* xptr = x + (size_t)(bbase + xr) * (Tv * Dv) + xd;
    xs[xd * 32 + xr] = xptr[0];
    __syncthreads();

    float c0[8], c1[8];
    #pragma unroll
    for (int i = 0; i < 8; i++) { c0[i] = 0.0f; c1[i] = 0.0f; }

    ull acc0[16], acc1[16];

    // ---- prologue: stage (1) for t=0 ----
    init_acc(acc0, b0s, tg);
    gemm_acc<Dv, 32>(acc0, xs, Wx0, hoff, tg);          // xcur = buf0
    float xreg = __ldg(xptr + Dv);                      // x(t=1)
    gemm_acc<Hv, HS>(acc0, ht0, Wt0, hoff, tg);         // h0 = 0, fine

    for (int t = 0; t < Tv; t++) {
        float* xnxt = xs + ((t + 1) & 1) * 256;

        GBAR(gbar);                                     // group: ht0-old/xcur reads done; prev ht1' visible

        // (2) layer-0 cell (MUFU) — overlaps (3)'s independent GEMM on acc1
        cell_update(acc0, c0, ht0 + tg * HS + hoff);    // write new h0
        xnxt[xd * 32 + xr] = xreg;                      // stage x(t+1)

        // (3) layer-1 recurrent GEMM: acc1 = b1 + h1_prev @ Whh1^T
        init_acc(acc1, b1s, tg);
        gemm_acc<Hv, HS>(acc1, ht1, Wt1, hoff, tg);

        GBAR(gbar);                                     // group: h0' + xnxt visible; ht1-old reads done

        // (5) acc1 += h0' @ Wih1^T ; layer-1 cell (MUFU overlaps (6) GEMM on acc0)
        gemm_acc<Hv, HS>(acc1, ht0, Wi1, hoff, tg);
        cell_update(acc1, c1, ht1 + tg * HS + hoff);    // write new h1

        // (6) next step's layer-0 stage (rotated into this body; wasted on t=Tv-1)
        init_acc(acc0, b0s, tg);
        gemm_acc<Dv, 32>(acc0, xnxt, Wx0, hoff, tg);
        if (t + 2 < Tv) xreg = __ldg(xptr + (size_t)(t + 2) * Dv);
        gemm_acc<Hv, HS>(acc0, ht0, Wt0, hoff, tg);
    }
    __syncthreads();                                    // all groups' final h1 visible for FC

    // ---- FC: out[b] = h1_final[b,:] . Wfc + bfc ----
    if (tid < TILE_B) {
        float s = 0.0f;
        #pragma unroll
        for (int j = 0; j < Hv; j++) s += ht1[j * HS + tid] * __ldg(Wfc + j);
        out[bbase + tid] = s + __ldg(bfc);
    }
}

extern "C" void kernel_launch(void* const* d_in, const int* in_sizes, int n_in,
                              void* d_out, int out_size)
{
    const float* x    = (const float*)d_in[0];
    const float* Wih0 = (const float*)d_in[1];
    const float* Whh0 = (const float*)d_in[2];
    const float* bih0 = (const float*)d_in[3];
    const float* bhh0 = (const float*)d_in[4];
    const float* Wih1 = (const float*)d_in[5];
    const float* Whh1 = (const float*)d_in[6];
    const float* bih1 = (const float*)d_in[7];
    const float* bhh1 = (const float*)d_in[8];
    const float* Wfc  = (const float*)d_in[9];
    const float* bfc  = (const float*)d_in[10];
    float* out = (float*)d_out;

    size_t shm = (size_t)SMEM_FLOATS * sizeof(float);   // 227328 B
    cudaFuncSetAttribute(lstm_kernel, cudaFuncAttributeMaxDynamicSharedMemorySize, (int)shm);
    lstm_kernel<<<Bv / TILE_B, NTH, shm>>>(x, Wih0, Whh0, bih0, bhh0,
                                           Wih1, Whh1, bih1, bhh1, Wfc, bfc, out);
}

// round 13
// speedup vs baseline: 3.5043x; 3.0869x over previous
#include <cuda_runtime.h>
#include <cuda_fp16.h>
#include <cstdint>

// LSTMModel: 2-layer LSTM (B=4096,T=512,D=8,H=64) + FC(H->1).
// R12: warp-level HMMA (mma.sync.m16n8k16 f16->f32; base ISA, no sm_103a gating).
// 128 CTAs x 32 batch. Warp w owns gates j in [8w,8w+8) for all 4 gate types via
// gate-row permutation -> cell update is register-local (no exchange).
// W fp16 fragments preloaded in registers; h,x split hi/lo fp16 in SMEM.

#define Bv 4096
#define Tv 512
#define Dv 8
#define Hv 64
#define TILE_B 32
#define NTH 256
#define HSB 144              // h row stride bytes ([batch][72 halves]) - conflict-free
#define XSB 48               // x row stride bytes ([batch][24 halves])

// SMEM byte offsets
#define H0HI 0               // [32][HSB]
#define H0LO 4608
#define H1HI 9216
#define H1LO 13824
#define XBUF 18432           // [32][XSB]; hi at k=0..7, lo at k=8..15
#define SMEM_BYTES 19968

__device__ __forceinline__ float tanh_(float x) {
    float r; asm("tanh.approx.f32 %0, %1;" : "=f"(r) : "f"(x)); return r;
}
__device__ __forceinline__ float sig_(float x) {
    return fmaf(tanh_(0.5f * x), 0.5f, 0.5f);
}

__device__ __forceinline__ void mma16816(float* d, const uint32_t* a, const uint32_t* b) {
    asm volatile(
        "mma.sync.aligned.m16n8k16.row.col.f32.f16.f16.f32 "
        "{%0,%1,%2,%3}, {%4,%5,%6,%7}, {%8,%9}, {%0,%1,%2,%3};"
        : "+f"(d[0]), "+f"(d[1]), "+f"(d[2]), "+f"(d[3])
        : "r"(a[0]), "r"(a[1]), "r"(a[2]), "r"(a[3]), "r"(b[0]), "r"(b[1]));
}

__device__ __forceinline__ uint32_t packW(const float* W, int ncols, int g, int k) {
    __half2 v = __halves2half2(__float2half_rn(W[g * ncols + k]),
                               __float2half_rn(W[g * ncols + k + 1]));
    return *reinterpret_cast<uint32_t*>(&v);
}

// B fragment: b0 = h[n=grp][k=tig*2..+1], b1 = same n, k+8. addr 4B-aligned.
__device__ __forceinline__ void ldB(uint32_t* b, const char* p) {
    b[0] = *(const uint32_t*)p;
    b[1] = *(const uint32_t*)(p + 16);
}

// acc[mt][nt][4] += W(frags aW[mt][kt][4]) @ h(hbase buffer)
__device__ __forceinline__ void gemm(float acc[2][4][4], const uint32_t aW[2][4][4],
                                     const char* smc, int hbase, int grp, int tig)
{
    const char* base = smc + hbase + grp * HSB + tig * 4;
    #pragma unroll
    for (int kt = 0; kt < 4; kt++) {
        #pragma unroll
        for (int nt = 0; nt < 4; nt++) {
            uint32_t b[2];
            ldB(b, base + nt * (8 * HSB) + kt * 32);
            mma16816(acc[0][nt], aW[0][kt], b);
            mma16816(acc[1][nt], aW[1][kt], b);
        }
    }
}

__global__ void __launch_bounds__(NTH, 1)
lstm_hmma_kernel(const float* __restrict__ x,
                 const float* __restrict__ Wih0, const float* __restrict__ Whh0,
                 const float* __restrict__ bih0, const float* __restrict__ bhh0,
                 const float* __restrict__ Wih1, const float* __restrict__ Whh1,
                 const float* __restrict__ bih1, const float* __restrict__ bhh1,
                 const float* __restrict__ Wfc,  const float* __restrict__ bfc,
                 float* __restrict__ out)
{
    extern __shared__ char smc[];
    const int tid  = threadIdx.x;
    const int wid  = tid >> 5;
    const int lane = tid & 31;
    const int grp  = lane >> 2;          // 0..7
    const int tig  = lane & 3;           // 0..3
    const int j    = (wid << 3) + grp;   // this thread's hidden index (both m-tiles)
    const int bbase = blockIdx.x * TILE_B;

    // ---- preload W fragments into registers ----
    // m-tile mt rows 0-7 -> gate q=2mt (i / g), rows 8-15 -> q=2mt+1 (f / o).
    uint32_t aHH0[2][4][4], aIH1[2][4][4], aHH1[2][4][4], aX[2][2];
    #pragma unroll
    for (int mt = 0; mt < 2; mt++) {
        #pragma unroll
        for (int kt = 0; kt < 4; kt++) {
            int k = kt * 16 + tig * 2;
            int g0 = (2 * mt + 0) * 64 + j;
            int g1 = (2 * mt + 1) * 64 + j;
            aHH0[mt][kt][0] = packW(Whh0, 64, g0, k);
            aHH0[mt][kt][1] = packW(Whh0, 64, g1, k);
            aHH0[mt][kt][2] = packW(Whh0, 64, g0, k + 8);
            aHH0[mt][kt][3] = packW(Whh0, 64, g1, k + 8);
            aIH1[mt][kt][0] = packW(Wih1, 64, g0, k);
            aIH1[mt][kt][1] = packW(Wih1, 64, g1, k);
            aIH1[mt][kt][2] = packW(Wih1, 64, g0, k + 8);
            aIH1[mt][kt][3] = packW(Wih1, 64, g1, k + 8);
            aHH1[mt][kt][0] = packW(Whh1, 64, g0, k);
            aHH1[mt][kt][1] = packW(Whh1, 64, g1, k);
            aHH1[mt][kt][2] = packW(Whh1, 64, g0, k + 8);
            aHH1[mt][kt][3] = packW(Whh1, 64, g1, k + 8);
        }
        // x GEMM: K=16 tile, k0..7 = x_hi, k8..15 = x_lo; A duplicated -> a2=a0, a3=a1.
        aX[mt][0] = packW(Wih0, 8, (2 * mt + 0) * 64 + j, tig * 2);
        aX[mt][1] = packW(Wih0, 8, (2 * mt + 1) * 64 + j, tig * 2);
    }
    // biases for this thread's j (gate order i,f,g,o)
    const float bI0 = bih0[j]       + bhh0[j];
    const float bF0 = bih0[64 + j]  + bhh0[64 + j];
    const float bG0 = bih0[128 + j] + bhh0[128 + j];
    const float bO0 = bih0[192 + j] + bhh0[192 + j];
    const float bI1 = bih1[j]       + bhh1[j];
    const float bF1 = bih1[64 + j]  + bhh1[64 + j];
    const float bG1 = bih1[128 + j] + bhh1[128 + j];
    const float bO1 = bih1[192 + j] + bhh1[192 + j];

    // zero h buffers + x buf
    for (int i = tid; i < SMEM_BYTES / 4; i += NTH) ((uint32_t*)smc)[i] = 0u;

    // stage x(0)
    const int xb = tid >> 3, xd = tid & 7;
    const float* xptr = x + (size_t)(bbase + xb) * (Tv * Dv) + xd;
    {
        float v = xptr[0];
        __half hh = __float2half_rn(v);
        __half hl = __float2half_rn(v - __half2float(hh));
        *(__half*)(smc + XBUF + xb * XSB + xd * 2)      = hh;
        *(__half*)(smc + XBUF + xb * XSB + (8 + xd) * 2) = hl;
    }
    __syncthreads();

    float c0[8], c1[8];
    #pragma unroll
    for (int i = 0; i < 8; i++) { c0[i] = 0.0f; c1[i] = 0.0f; }
    float xreg = __ldg(xptr + Dv);

    float acc[2][4][4];

    for (int t = 0; t < Tv; t++) {
        // ---- layer 0: acc = Wx*[x_hi;x_lo] + Whh0*h0_hi + Whh0*h0_lo ----
        #pragma unroll
        for (int mt = 0; mt < 2; mt++)
            #pragma unroll
            for (int nt = 0; nt < 4; nt++)
                #pragma unroll
                for (int e = 0; e < 4; e++) acc[mt][nt][e] = 0.0f;
        {
            const char* xb0 = smc + XBUF + grp * XSB + tig * 4;
            #pragma unroll
            for (int nt = 0; nt < 4; nt++) {
                uint32_t b[2];
                ldB(b, xb0 + nt * (8 * XSB));
                uint32_t a0[4] = { aX[0][0], aX[0][1], aX[0][0], aX[0][1] };
                uint32_t a1[4] = { aX[1][0], aX[1][1], aX[1][0], aX[1][1] };
                mma16816(acc[0][nt], a0, b);
                mma16816(acc[1][nt], a1, b);
            }
        }
        gemm(acc, aHH0, smc, H0HI, grp, tig);
        gemm(acc, aHH0, smc, H0LO, grp, tig);
        __syncthreads();                       // (A) reads of h0_old + x(t) done

        // ---- layer-0 cell (register-local) -> write h0' ----
        #pragma unroll
        for (int nt = 0; nt < 4; nt++)
            #pragma unroll
            for (int e = 0; e < 2; e++) {
                float zi = acc[0][nt][e]     + bI0;
                float zf = acc[0][nt][2 + e] + bF0;
                float zg = acc[1][nt][e]     + bG0;
                float zo = acc[1][nt][2 + e] + bO0;
                int ci = nt * 2 + e;
                float cn = sig_(zf) * c0[ci] + sig_(zi) * tanh_(zg);
                c0[ci] = cn;
                float h = sig_(zo) * tanh_(cn);
                __half hh = __float2half_rn(h);
                __half hl = __float2half_rn(h - __half2float(hh));
                int bcol = nt * 8 + tig * 2 + e;
                *(__half*)(smc + H0HI + bcol * HSB + j * 2) = hh;
                *(__half*)(smc + H0LO + bcol * HSB + j * 2) = hl;
            }
        if (t + 1 < Tv) {                      // stage x(t+1)
            __half hh = __float2half_rn(xreg);
            __half hl = __float2half_rn(xreg - __half2float(hh));
            *(__half*)(smc + XBUF + xb * XSB + xd * 2)       = hh;
            *(__half*)(smc + XBUF + xb * XSB + (8 + xd) * 2) = hl;
            if (t + 2 < Tv) xreg = __ldg(xptr + (size_t)(t + 2) * Dv);
        }
        __syncthreads();                       // (B) h0' + x(t+1) visible

        // ---- layer 1: acc = Wih1*h0' + Whh1*h1_old ----
        #pragma unroll
        for (int mt = 0; mt < 2; mt++)
            #pragma unroll
            for (int nt = 0; nt < 4; nt++)
                #pragma unroll
                for (int e = 0; e < 4; e++) acc[mt][nt][e] = 0.0f;
        gemm(acc, aIH1, smc, H0HI, grp, tig);
        gemm(acc, aIH1, smc, H0LO, grp, tig);
        gemm(acc, aHH1, smc, H1HI, grp, tig);
        gemm(acc, aHH1, smc, H1LO, grp, tig);
        __syncthreads();                       // (C) reads of h1_old done

        // ---- layer-1 cell -> write h1' ----
        #pragma unroll
        for (int nt = 0; nt < 4; nt++)
            #pragma unroll
            for (int e = 0; e < 2; e++) {
                float zi = acc[0][nt][e]     + bI1;
                float zf = acc[0][nt][2 + e] + bF1;
                float zg = acc[1][nt][e]     + bG1;
                float zo = acc[1][nt][2 + e] + bO1;
                int ci = nt * 2 + e;
                float cn = sig_(zf) * c1[ci] + sig_(zi) * tanh_(zg);
                c1[ci] = cn;
                float h = sig_(zo) * tanh_(cn);
                __half hh = __float2half_rn(h);
                __half hl = __float2half_rn(h - __half2float(hh));
                int bcol = nt * 8 + tig * 2 + e;
                *(__half*)(smc + H1HI + bcol * HSB + j * 2) = hh;
                *(__half*)(smc + H1LO + bcol * HSB + j * 2) = hl;
            }
        // next step's (A)/(B) order h1' reads; WAR covered by (C) next step.
    }
    __syncthreads();                           // final h1 visible for FC

    // ---- FC: out[b] = sum_j (h1hi+h1lo)[b][j] * Wfc[j] + bfc ----
    if (tid < TILE_B) {
        float s = 0.0f;
        #pragma unroll
        for (int jj = 0; jj < Hv; jj++) {
            float h = __half2float(*(__half*)(smc + H1HI + tid * HSB + jj * 2))
                    + __half2float(*(__half*)(smc + H1LO + tid * HSB + jj * 2));
            s += h * __ldg(Wfc + jj);
        }
        out[bbase + tid] = s + __ldg(bfc);
    }
}

extern "C" void kernel_launch(void* const* d_in, const int* in_sizes, int n_in,
                              void* d_out, int out_size)
{
    const float* x    = (const float*)d_in[0];
    const float* Wih0 = (const float*)d_in[1];
    const float* Whh0 = (const float*)d_in[2];
    const float* bih0 = (const float*)d_in[3];
    const float* bhh0 = (const float*)d_in[4];
    const float* Wih1 = (const float*)d_in[5];
    const float* Whh1 = (const float*)d_in[6];
    const float* bih1 = (const float*)d_in[7];
    const float* bhh1 = (const float*)d_in[8];
    const float* Wfc  = (const float*)d_in[9];
    const float* bfc  = (const float*)d_in[10];
    float* out = (float*)d_out;

    cudaFuncSetAttribute(lstm_hmma_kernel, cudaFuncAttributeMaxDynamicSharedMemorySize,
                         SMEM_BYTES);
    lstm_hmma_kernel<<<Bv / TILE_B, NTH, SMEM_BYTES>>>(x, Wih0, Whh0, bih0, bhh0,
                                                       Wih1, Whh1, bih1, bhh1,
                                                       Wfc, bfc, out);
}

// round 14
// speedup vs baseline: 3.8346x; 1.0943x over previous
#include <cuda_runtime.h>
#include <cuda_fp16.h>
#include <cstdint>

// LSTMModel: 2-layer LSTM (B=4096,T=512,D=8,H=64) + FC(H->1).
// R14: HMMA path, 2 syncs/step (was 3). Layer-1 recurrent GEMM hoisted next to
// cell0; cell1 overlaps next step's layer-0 GEMMs (no trailing barrier).
// Accumulators init to bias. W fp16 frags in registers; h,x split hi/lo fp16.

#define Bv 4096
#define Tv 512
#define Dv 8
#define Hv 64
#define TILE_B 32
#define NTH 256
#define HSB 144              // h row stride bytes ([batch][72 halves]) - conflict-free
#define XSB 48               // x row stride bytes ([batch][24 halves])

// SMEM byte offsets
#define H0HI 0               // [32][HSB]
#define H0LO 4608
#define H1HI 9216
#define H1LO 13824
#define XBUF 18432           // [32][XSB]; hi at k=0..7, lo at k=8..15
#define SMEM_BYTES 19968

__device__ __forceinline__ float tanh_(float x) {
    float r; asm("tanh.approx.f32 %0, %1;" : "=f"(r) : "f"(x)); return r;
}
__device__ __forceinline__ float sig_(float x) {
    return fmaf(tanh_(0.5f * x), 0.5f, 0.5f);
}

__device__ __forceinline__ void mma16816(float* d, const uint32_t* a, const uint32_t* b) {
    asm volatile(
        "mma.sync.aligned.m16n8k16.row.col.f32.f16.f16.f32 "
        "{%0,%1,%2,%3}, {%4,%5,%6,%7}, {%8,%9}, {%0,%1,%2,%3};"
        : "+f"(d[0]), "+f"(d[1]), "+f"(d[2]), "+f"(d[3])
        : "r"(a[0]), "r"(a[1]), "r"(a[2]), "r"(a[3]), "r"(b[0]), "r"(b[1]));
}

__device__ __forceinline__ uint32_t packW(const float* W, int ncols, int g, int k) {
    __half2 v = __halves2half2(__float2half_rn(W[g * ncols + k]),
                               __float2half_rn(W[g * ncols + k + 1]));
    return *reinterpret_cast<uint32_t*>(&v);
}

__device__ __forceinline__ void ldB(uint32_t* b, const char* p) {
    b[0] = *(const uint32_t*)p;
    b[1] = *(const uint32_t*)(p + 16);
}

// acc[mt][nt][4] += W(frags aW[mt][kt][4]) @ h(hbase buffer)
__device__ __forceinline__ void gemm(float acc[2][4][4], const uint32_t aW[2][4][4],
                                     const char* smc, int hbase, int grp, int tig)
{
    const char* base = smc + hbase + grp * HSB + tig * 4;
    #pragma unroll
    for (int kt = 0; kt < 4; kt++) {
        #pragma unroll
        for (int nt = 0; nt < 4; nt++) {
            uint32_t b[2];
            ldB(b, base + nt * (8 * HSB) + kt * 32);
            mma16816(acc[0][nt], aW[0][kt], b);
            mma16816(acc[1][nt], aW[1][kt], b);
        }
    }
}

__global__ void __launch_bounds__(NTH, 1)
lstm_hmma_kernel(const float* __restrict__ x,
                 const float* __restrict__ Wih0, const float* __restrict__ Whh0,
                 const float* __restrict__ bih0, const float* __restrict__ bhh0,
                 const float* __restrict__ Wih1, const float* __restrict__ Whh1,
                 const float* __restrict__ bih1, const float* __restrict__ bhh1,
                 const float* __restrict__ Wfc,  const float* __restrict__ bfc,
                 float* __restrict__ out)
{
    extern __shared__ char smc[];
    const int tid  = threadIdx.x;
    const int wid  = tid >> 5;
    const int lane = tid & 31;
    const int grp  = lane >> 2;          // 0..7
    const int tig  = lane & 3;           // 0..3
    const int j    = (wid << 3) + grp;   // this thread's hidden index (both m-tiles)
    const int bbase = blockIdx.x * TILE_B;

    // ---- preload W fragments into registers ----
    // m-tile mt rows 0-7 -> gate q=2mt (i / g), rows 8-15 -> q=2mt+1 (f / o).
    uint32_t aHH0[2][4][4], aIH1[2][4][4], aHH1[2][4][4], aX[2][2];
    #pragma unroll
    for (int mt = 0; mt < 2; mt++) {
        #pragma unroll
        for (int kt = 0; kt < 4; kt++) {
            int k = kt * 16 + tig * 2;
            int g0 = (2 * mt + 0) * 64 + j;
            int g1 = (2 * mt + 1) * 64 + j;
            aHH0[mt][kt][0] = packW(Whh0, 64, g0, k);
            aHH0[mt][kt][1] = packW(Whh0, 64, g1, k);
            aHH0[mt][kt][2] = packW(Whh0, 64, g0, k + 8);
            aHH0[mt][kt][3] = packW(Whh0, 64, g1, k + 8);
            aIH1[mt][kt][0] = packW(Wih1, 64, g0, k);
            aIH1[mt][kt][1] = packW(Wih1, 64, g1, k);
            aIH1[mt][kt][2] = packW(Wih1, 64, g0, k + 8);
            aIH1[mt][kt][3] = packW(Wih1, 64, g1, k + 8);
            aHH1[mt][kt][0] = packW(Whh1, 64, g0, k);
            aHH1[mt][kt][1] = packW(Whh1, 64, g1, k);
            aHH1[mt][kt][2] = packW(Whh1, 64, g0, k + 8);
            aHH1[mt][kt][3] = packW(Whh1, 64, g1, k + 8);
        }
        aX[mt][0] = packW(Wih0, 8, (2 * mt + 0) * 64 + j, tig * 2);
        aX[mt][1] = packW(Wih0, 8, (2 * mt + 1) * 64 + j, tig * 2);
    }
    // biases for this thread's j (i,f in m-tile0; g,o in m-tile1)
    const float bI0 = bih0[j]       + bhh0[j];
    const float bF0 = bih0[64 + j]  + bhh0[64 + j];
    const float bG0 = bih0[128 + j] + bhh0[128 + j];
    const float bO0 = bih0[192 + j] + bhh0[192 + j];
    const float bI1 = bih1[j]       + bhh1[j];
    const float bF1 = bih1[64 + j]  + bhh1[64 + j];
    const float bG1 = bih1[128 + j] + bhh1[128 + j];
    const float bO1 = bih1[192 + j] + bhh1[192 + j];

    // zero h buffers + x buf
    for (int i = tid; i < SMEM_BYTES / 4; i += NTH) ((uint32_t*)smc)[i] = 0u;

    // stage x(0)
    const int xb = tid >> 3, xd = tid & 7;
    const float* xptr = x + (size_t)(bbase + xb) * (Tv * Dv) + xd;
    {
        float v = xptr[0];
        __half hh = __float2half_rn(v);
        __half hl = __float2half_rn(v - __half2float(hh));
        *(__half*)(smc + XBUF + xb * XSB + xd * 2)       = hh;
        *(__half*)(smc + XBUF + xb * XSB + (8 + xd) * 2) = hl;
    }
    __syncthreads();

    float c0[8], c1[8];
    #pragma unroll
    for (int i = 0; i < 8; i++) { c0[i] = 0.0f; c1[i] = 0.0f; }
    float xreg = __ldg(xptr + Dv);

    float acc[2][4][4];

    for (int t = 0; t < Tv; t++) {
        // ---- layer 0: acc = bias0 + Wx*[x_hi;x_lo] + Whh0*(h0_hi + h0_lo) ----
        #pragma unroll
        for (int nt = 0; nt < 4; nt++) {
            acc[0][nt][0] = bI0; acc[0][nt][1] = bI0;
            acc[0][nt][2] = bF0; acc[0][nt][3] = bF0;
            acc[1][nt][0] = bG0; acc[1][nt][1] = bG0;
            acc[1][nt][2] = bO0; acc[1][nt][3] = bO0;
        }
        {
            const char* xb0 = smc + XBUF + grp * XSB + tig * 4;
            #pragma unroll
            for (int nt = 0; nt < 4; nt++) {
                uint32_t b[2];
                ldB(b, xb0 + nt * (8 * XSB));
                uint32_t a0[4] = { aX[0][0], aX[0][1], aX[0][0], aX[0][1] };
                uint32_t a1[4] = { aX[1][0], aX[1][1], aX[1][0], aX[1][1] };
                mma16816(acc[0][nt], a0, b);
                mma16816(acc[1][nt], a1, b);
            }
        }
        gemm(acc, aHH0, smc, H0HI, grp, tig);
        gemm(acc, aHH0, smc, H0LO, grp, tig);
        __syncthreads();                       // (A) h0_old/x reads done; h1'(t-1) visible

        // ---- layer-0 cell (MUFU) -> write h0'; overlaps acc1 recurrent GEMM below ----
        float hcell0[8];
        #pragma unroll
        for (int nt = 0; nt < 4; nt++)
            #pragma unroll
            for (int e = 0; e < 2; e++) {
                float zi = acc[0][nt][e];
                float zf = acc[0][nt][2 + e];
                float zg = acc[1][nt][e];
                float zo = acc[1][nt][2 + e];
                int ci = nt * 2 + e;
                float cn = sig_(zf) * c0[ci] + sig_(zi) * tanh_(zg);
                c0[ci] = cn;
                hcell0[ci] = sig_(zo) * tanh_(cn);
            }

        // ---- layer-1 recurrent: acc = bias1 + Whh1*(h1_old hi+lo) ----
        #pragma unroll
        for (int nt = 0; nt < 4; nt++) {
            acc[0][nt][0] = bI1; acc[0][nt][1] = bI1;
            acc[0][nt][2] = bF1; acc[0][nt][3] = bF1;
            acc[1][nt][0] = bG1; acc[1][nt][1] = bG1;
            acc[1][nt][2] = bO1; acc[1][nt][3] = bO1;
        }
        gemm(acc, aHH1, smc, H1HI, grp, tig);
        gemm(acc, aHH1, smc, H1LO, grp, tig);

        // h0' writeback + x(t+1) staging (LSU; interleaves with GEMM above)
        #pragma unroll
        for (int nt = 0; nt < 4; nt++)
            #pragma unroll
            for (int e = 0; e < 2; e++) {
                float h = hcell0[nt * 2 + e];
                __half hh = __float2half_rn(h);
                __half hl = __float2half_rn(h - __half2float(hh));
                int bcol = nt * 8 + tig * 2 + e;
                *(__half*)(smc + H0HI + bcol * HSB + j * 2) = hh;
                *(__half*)(smc + H0LO + bcol * HSB + j * 2) = hl;
            }
        if (t + 1 < Tv) {
            __half hh = __float2half_rn(xreg);
            __half hl = __float2half_rn(xreg - __half2float(hh));
            *(__half*)(smc + XBUF + xb * XSB + xd * 2)       = hh;
            *(__half*)(smc + XBUF + xb * XSB + (8 + xd) * 2) = hl;
            if (t + 2 < Tv) xreg = __ldg(xptr + (size_t)(t + 2) * Dv);
        }
        __syncthreads();                       // (B) h0'+x(t+1) visible; h1_old reads done

        // ---- layer 1 input part + cell ----
        gemm(acc, aIH1, smc, H0HI, grp, tig);
        gemm(acc, aIH1, smc, H0LO, grp, tig);
        #pragma unroll
        for (int nt = 0; nt < 4; nt++)
            #pragma unroll
            for (int e = 0; e < 2; e++) {
                float zi = acc[0][nt][e];
                float zf = acc[0][nt][2 + e];
                float zg = acc[1][nt][e];
                float zo = acc[1][nt][2 + e];
                int ci = nt * 2 + e;
                float cn = sig_(zf) * c1[ci] + sig_(zi) * tanh_(zg);
                c1[ci] = cn;
                float h = sig_(zo) * tanh_(cn);
                __half hh = __float2half_rn(h);
                __half hl = __float2half_rn(h - __half2float(hh));
                int bcol = nt * 8 + tig * 2 + e;
                *(__half*)(smc + H1HI + bcol * HSB + j * 2) = hh;
                *(__half*)(smc + H1LO + bcol * HSB + j * 2) = hl;
            }
        // no trailing sync: h1' RAW for t+1 covered by (A); WAR on h1 covered by (B).
        // cell1 MUFUs overlap next iteration's layer-0 GEMM issue.
    }
    __syncthreads();                           // final h1 visible for FC

    // ---- FC: out[b] = sum_j (h1hi+h1lo)[b][j] * Wfc[j] + bfc ----
    if (tid < TILE_B) {
        float s = 0.0f;
        #pragma unroll
        for (int jj = 0; jj < Hv; jj++) {
            float h = __half2float(*(__half*)(smc + H1HI + tid * HSB + jj * 2))
                    + __half2float(*(__half*)(smc + H1LO + tid * HSB + jj * 2));
            s += h * __ldg(Wfc + jj);
        }
        out[bbase + tid] = s + __ldg(bfc);
    }
}

extern "C" void kernel_launch(void* const* d_in, const int* in_sizes, int n_in,
                              void* d_out, int out_size)
{
    const float* x    = (const float*)d_in[0];
    const float* Wih0 = (const float*)d_in[1];
    const float* Whh0 = (const float*)d_in[2];
    const float* bih0 = (const float*)d_in[3];
    const float* bhh0 = (const float*)d_in[4];
    const float* Wih1 = (const float*)d_in[5];
    const float* Whh1 = (const float*)d_in[6];
    const float* bih1 = (const float*)d_in[7];
    const float* bhh1 = (const float*)d_in[8];
    const float* Wfc  = (const float*)d_in[9];
    const float* bfc  = (const float*)d_in[10];
    float* out = (float*)d_out;

    cudaFuncSetAttribute(lstm_hmma_kernel, cudaFuncAttributeMaxDynamicSharedMemorySize,
                         SMEM_BYTES);
    lstm_hmma_kernel<<<Bv / TILE_B, NTH, SMEM_BYTES>>>(x, Wih0, Whh0, bih0, bhh0,
                                                       Wih1, Whh1, bih1, bhh1,
                                                       Wfc, bfc, out);
}

// round 15
// speedup vs baseline: 6.2313x; 1.6250x over previous
#include <cuda_runtime.h>
#include <cuda_fp16.h>
#include <cstdint>

// LSTMModel: 2-layer LSTM (B=4096,T=512,D=8,H=64) + FC(H->1).
// R15: HMMA path; h stored single fp16 (lo-split dropped: error budget ~1e-4
// added, ~2x margin under 1e-3). x keeps hi/lo split (cheap, one K=16 block).
// 104 MMAs/warp/step (was 200). 2 CTA syncs/step; W fp16 frags in registers.

#define Bv 4096
#define Tv 512
#define Dv 8
#define Hv 64
#define TILE_B 32
#define NTH 256
#define HSB 144              // h row stride bytes ([batch][72 halves]) - conflict-free
#define XSB 48               // x row stride bytes ([batch][24 halves])

// SMEM byte offsets
#define H0BUF 0              // [32][HSB] fp16
#define H1BUF 4608
#define XBUF  9216           // [32][XSB]; hi at k=0..7, lo at k=8..15
#define SMEM_BYTES 10752

__device__ __forceinline__ float tanh_(float x) {
    float r; asm("tanh.approx.f32 %0, %1;" : "=f"(r) : "f"(x)); return r;
}
__device__ __forceinline__ float sig_(float x) {
    return fmaf(tanh_(0.5f * x), 0.5f, 0.5f);
}

__device__ __forceinline__ void mma16816(float* d, const uint32_t* a, const uint32_t* b) {
    asm volatile(
        "mma.sync.aligned.m16n8k16.row.col.f32.f16.f16.f32 "
        "{%0,%1,%2,%3}, {%4,%5,%6,%7}, {%8,%9}, {%0,%1,%2,%3};"
        : "+f"(d[0]), "+f"(d[1]), "+f"(d[2]), "+f"(d[3])
        : "r"(a[0]), "r"(a[1]), "r"(a[2]), "r"(a[3]), "r"(b[0]), "r"(b[1]));
}

__device__ __forceinline__ uint32_t packW(const float* W, int ncols, int g, int k) {
    __half2 v = __halves2half2(__float2half_rn(W[g * ncols + k]),
                               __float2half_rn(W[g * ncols + k + 1]));
    return *reinterpret_cast<uint32_t*>(&v);
}

__device__ __forceinline__ void ldB(uint32_t* b, const char* p) {
    b[0] = *(const uint32_t*)p;
    b[1] = *(const uint32_t*)(p + 16);
}

// acc[mt][nt][4] += W(frags aW[mt][kt][4]) @ h(hbase buffer), K=64
__device__ __forceinline__ void gemm(float acc[2][4][4], const uint32_t aW[2][4][4],
                                     const char* smc, int hbase, int grp, int tig)
{
    const char* base = smc + hbase + grp * HSB + tig * 4;
    #pragma unroll
    for (int kt = 0; kt < 4; kt++) {
        #pragma unroll
        for (int nt = 0; nt < 4; nt++) {
            uint32_t b[2];
            ldB(b, base + nt * (8 * HSB) + kt * 32);
            mma16816(acc[0][nt], aW[0][kt], b);
            mma16816(acc[1][nt], aW[1][kt], b);
        }
    }
}

__global__ void __launch_bounds__(NTH, 1)
lstm_hmma_kernel(const float* __restrict__ x,
                 const float* __restrict__ Wih0, const float* __restrict__ Whh0,
                 const float* __restrict__ bih0, const float* __restrict__ bhh0,
                 const float* __restrict__ Wih1, const float* __restrict__ Whh1,
                 const float* __restrict__ bih1, const float* __restrict__ bhh1,
                 const float* __restrict__ Wfc,  const float* __restrict__ bfc,
                 float* __restrict__ out)
{
    extern __shared__ char smc[];
    const int tid  = threadIdx.x;
    const int wid  = tid >> 5;
    const int lane = tid & 31;
    const int grp  = lane >> 2;          // 0..7
    const int tig  = lane & 3;           // 0..3
    const int j    = (wid << 3) + grp;   // this thread's hidden index
    const int bbase = blockIdx.x * TILE_B;

    // ---- preload W fragments (m-tile0 rows: gates i|f ; m-tile1: g|o) ----
    uint32_t aHH0[2][4][4], aIH1[2][4][4], aHH1[2][4][4], aX[2][2];
    #pragma unroll
    for (int mt = 0; mt < 2; mt++) {
        #pragma unroll
        for (int kt = 0; kt < 4; kt++) {
            int k = kt * 16 + tig * 2;
            int g0 = (2 * mt + 0) * 64 + j;
            int g1 = (2 * mt + 1) * 64 + j;
            aHH0[mt][kt][0] = packW(Whh0, 64, g0, k);
            aHH0[mt][kt][1] = packW(Whh0, 64, g1, k);
            aHH0[mt][kt][2] = packW(Whh0, 64, g0, k + 8);
            aHH0[mt][kt][3] = packW(Whh0, 64, g1, k + 8);
            aIH1[mt][kt][0] = packW(Wih1, 64, g0, k);
            aIH1[mt][kt][1] = packW(Wih1, 64, g1, k);
            aIH1[mt][kt][2] = packW(Wih1, 64, g0, k + 8);
            aIH1[mt][kt][3] = packW(Wih1, 64, g1, k + 8);
            aHH1[mt][kt][0] = packW(Whh1, 64, g0, k);
            aHH1[mt][kt][1] = packW(Whh1, 64, g1, k);
            aHH1[mt][kt][2] = packW(Whh1, 64, g0, k + 8);
            aHH1[mt][kt][3] = packW(Whh1, 64, g1, k + 8);
        }
        aX[mt][0] = packW(Wih0, 8, (2 * mt + 0) * 64 + j, tig * 2);
        aX[mt][1] = packW(Wih0, 8, (2 * mt + 1) * 64 + j, tig * 2);
    }
    const float bI0 = bih0[j]       + bhh0[j];
    const float bF0 = bih0[64 + j]  + bhh0[64 + j];
    const float bG0 = bih0[128 + j] + bhh0[128 + j];
    const float bO0 = bih0[192 + j] + bhh0[192 + j];
    const float bI1 = bih1[j]       + bhh1[j];
    const float bF1 = bih1[64 + j]  + bhh1[64 + j];
    const float bG1 = bih1[128 + j] + bhh1[128 + j];
    const float bO1 = bih1[192 + j] + bhh1[192 + j];

    // zero h buffers + x buf
    for (int i = tid; i < SMEM_BYTES / 4; i += NTH) ((uint32_t*)smc)[i] = 0u;

    // stage x(0) hi/lo
    const int xb = tid >> 3, xd = tid & 7;
    const float* xptr = x + (size_t)(bbase + xb) * (Tv * Dv) + xd;
    {
        float v = xptr[0];
        __half hh = __float2half_rn(v);
        __half hl = __float2half_rn(v - __half2float(hh));
        *(__half*)(smc + XBUF + xb * XSB + xd * 2)       = hh;
        *(__half*)(smc + XBUF + xb * XSB + (8 + xd) * 2) = hl;
    }
    __syncthreads();

    float c0[8], c1[8];
    #pragma unroll
    for (int i = 0; i < 8; i++) { c0[i] = 0.0f; c1[i] = 0.0f; }
    float xreg = __ldg(xptr + Dv);

    float acc[2][4][4];

    for (int t = 0; t < Tv; t++) {
        // ---- layer 0: acc = bias0 + Wx*[x_hi;x_lo] + Whh0*h0 ----
        #pragma unroll
        for (int nt = 0; nt < 4; nt++) {
            acc[0][nt][0] = bI0; acc[0][nt][1] = bI0;
            acc[0][nt][2] = bF0; acc[0][nt][3] = bF0;
            acc[1][nt][0] = bG0; acc[1][nt][1] = bG0;
            acc[1][nt][2] = bO0; acc[1][nt][3] = bO0;
        }
        {
            const char* xb0 = smc + XBUF + grp * XSB + tig * 4;
            #pragma unroll
            for (int nt = 0; nt < 4; nt++) {
                uint32_t b[2];
                ldB(b, xb0 + nt * (8 * XSB));
                uint32_t a0[4] = { aX[0][0], aX[0][1], aX[0][0], aX[0][1] };
                uint32_t a1[4] = { aX[1][0], aX[1][1], aX[1][0], aX[1][1] };
                mma16816(acc[0][nt], a0, b);
                mma16816(acc[1][nt], a1, b);
            }
        }
        gemm(acc, aHH0, smc, H0BUF, grp, tig);
        __syncthreads();                       // (A) h0_old/x reads done; h1'(t-1) visible

        // ---- layer-0 cell (MUFU) -> hcell0; overlaps layer-1 recurrent GEMM ----
        float hcell0[8];
        #pragma unroll
        for (int nt = 0; nt < 4; nt++)
            #pragma unroll
            for (int e = 0; e < 2; e++) {
                float zi = acc[0][nt][e];
                float zf = acc[0][nt][2 + e];
                float zg = acc[1][nt][e];
                float zo = acc[1][nt][2 + e];
                int ci = nt * 2 + e;
                float cn = sig_(zf) * c0[ci] + sig_(zi) * tanh_(zg);
                c0[ci] = cn;
                hcell0[ci] = sig_(zo) * tanh_(cn);
            }

        // ---- layer-1 recurrent: acc = bias1 + Whh1*h1_old ----
        #pragma unroll
        for (int nt = 0; nt < 4; nt++) {
            acc[0][nt][0] = bI1; acc[0][nt][1] = bI1;
            acc[0][nt][2] = bF1; acc[0][nt][3] = bF1;
            acc[1][nt][0] = bG1; acc[1][nt][1] = bG1;
            acc[1][nt][2] = bO1; acc[1][nt][3] = bO1;
        }
        gemm(acc, aHH1, smc, H1BUF, grp, tig);

        // h0' writeback + x(t+1) staging (LSU; interleaves with GEMM above)
        #pragma unroll
        for (int nt = 0; nt < 4; nt++)
            #pragma unroll
            for (int e = 0; e < 2; e++) {
                int bcol = nt * 8 + tig * 2 + e;
                *(__half*)(smc + H0BUF + bcol * HSB + j * 2) =
                    __float2half_rn(hcell0[nt * 2 + e]);
            }
        if (t + 1 < Tv) {
            __half hh = __float2half_rn(xreg);
            __half hl = __float2half_rn(xreg - __half2float(hh));
            *(__half*)(smc + XBUF + xb * XSB + xd * 2)       = hh;
            *(__half*)(smc + XBUF + xb * XSB + (8 + xd) * 2) = hl;
            if (t + 2 < Tv) xreg = __ldg(xptr + (size_t)(t + 2) * Dv);
        }
        __syncthreads();                       // (B) h0'+x(t+1) visible; h1_old reads done

        // ---- layer 1 input part + cell ----
        gemm(acc, aIH1, smc, H0BUF, grp, tig);
        #pragma unroll
        for (int nt = 0; nt < 4; nt++)
            #pragma unroll
            for (int e = 0; e < 2; e++) {
                float zi = acc[0][nt][e];
                float zf = acc[0][nt][2 + e];
                float zg = acc[1][nt][e];
                float zo = acc[1][nt][2 + e];
                int ci = nt * 2 + e;
                float cn = sig_(zf) * c1[ci] + sig_(zi) * tanh_(zg);
                c1[ci] = cn;
                float h = sig_(zo) * tanh_(cn);
                int bcol = nt * 8 + tig * 2 + e;
                *(__half*)(smc + H1BUF + bcol * HSB + j * 2) = __float2half_rn(h);
            }
        // no trailing sync: h1' RAW for t+1 covered by (A); WAR on h1 covered by (B).
    }
    __syncthreads();                           // final h1 visible for FC

    // ---- FC: out[b] = sum_j h1[b][j] * Wfc[j] + bfc ----
    if (tid < TILE_B) {
        float s = 0.0f;
        #pragma unroll
        for (int jj = 0; jj < Hv; jj++) {
            float h = __half2float(*(__half*)(smc + H1BUF + tid * HSB + jj * 2));
            s += h * __ldg(Wfc + jj);
        }
        out[bbase + tid] = s + __ldg(bfc);
    }
}

extern "C" void kernel_launch(void* const* d_in, const int* in_sizes, int n_in,
                              void* d_out, int out_size)
{
    const float* x    = (const float*)d_in[0];
    const float* Wih0 = (const float*)d_in[1];
    const float* Whh0 = (const float*)d_in[2];
    const float* bih0 = (const float*)d_in[3];
    const float* bhh0 = (const float*)d_in[4];
    const float* Wih1 = (const float*)d_in[5];
    const float* Whh1 = (const float*)d_in[6];
    const float* bih1 = (const float*)d_in[7];
    const float* bhh1 = (const float*)d_in[8];
    const float* Wfc  = (const float*)d_in[9];
    const float* bfc  = (const float*)d_in[10];
    float* out = (float*)d_out;

    cudaFuncSetAttribute(lstm_hmma_kernel, cudaFuncAttributeMaxDynamicSharedMemorySize,
                         SMEM_BYTES);
    lstm_hmma_kernel<<<Bv / TILE_B, NTH, SMEM_BYTES>>>(x, Wih0, Whh0, bih0, bhh0,
                                                       Wih1, Whh1, bih1, bhh1,
                                                       Wfc, bfc, out);
}